// round 8
// baseline (speedup 1.0000x reference)
#include <cuda_runtime.h>
#include <math.h>

#define NB   8
#define CC   256
#define HH   192
#define WW   320
#define FHH  768
#define FWW  1280
#define HWc  (HH*WW)          // 61440 coarse pixels
#define NHW  (NB*HWc)         // 491520
#define FHW  (FHH*FWW)        // 983040 fine pixels
#define FUSED_ELEMS ((size_t)NB*CC*HWc)   // 125,829,120
#define CH   16               // channels per block in fuse
#define CHUNKS (CC/CH)        // 16

// fuse tiling
#define TS_Y 8
#define TS_X 32
#define MARG 4
#define WIN_Y 16              // TS_Y + 2*MARG
#define WIN_X 40              // TS_X + 2*MARG
#define WIN_N (WIN_Y*WIN_X)   // 640
#define TILES ((HH/TS_Y)*(WW/TS_X))   // 240
#define STAGE_ITERS ((CH*WIN_N)/256)  // 40

// Precomputed per-(n,h,w):
//   g_w: (b*w00, b*w01, b*w10, b*w11) — bilinear weights * rm1n/s, invalid taps zeroed
//   g_o: (off00, dx, dyW, float_as_int(a)) — clamped tap base + steps + rm1/s
__device__ float4 g_w[NHW];
__device__ int4   g_o[NHW];

// -------------------------------------------------------------------------
// Kernel 1: per coarse pixel param computation.
// Bilinear resize 768x1280 -> 192x320 is exactly the mean of the 2x2 block
// at (4h+1, 4w+1) (fractional weights are exactly 0.5).
// -------------------------------------------------------------------------
__global__ void params_kernel(const float* __restrict__ flow,
                              const float* __restrict__ mask1,
                              const float* __restrict__ mask1n)
{
    int idx = blockIdx.x * blockDim.x + threadIdx.x;
    if (idx >= NHW) return;
    int w = idx % WW;
    int h = (idx / WW) % HH;
    int n = idx / HWc;

    size_t o00 = (size_t)(4*h + 1) * FWW + (4*w + 1);

    const float* flx = flow + (size_t)n * 2 * FHW;
    const float* fly = flx + (size_t)FHW;
    float rfx = 0.0625f * (flx[o00] + flx[o00+1] + flx[o00+FWW] + flx[o00+FWW+1]);
    float rfy = 0.0625f * (fly[o00] + fly[o00+1] + fly[o00+FWW] + fly[o00+FWW+1]);

    float px = ((float)w + rfx) * ((float)WW / (float)(WW-1)) - 0.5f;
    float py = ((float)h + rfy) * ((float)HH / (float)(HH-1)) - 0.5f;

    const float* m1 = mask1 + (size_t)n * FHW;
    float rm1 = 0.25f * (m1[o00] + m1[o00+1] + m1[o00+FWW] + m1[o00+FWW+1]);

    int   x0 = (int)floorf(px);
    int   y0 = (int)floorf(py);
    float wx = px - (float)x0;
    float wy = py - (float)y0;

    const float* mn = mask1n + (size_t)n * FHW;
    float v00 = 0.f, v01 = 0.f, v10 = 0.f, v11 = 0.f;
    bool yv0 = (y0 >= 0)   & (y0 < HH);
    bool yv1 = (y0+1 >= 0) & (y0+1 < HH);
    bool xv0 = (x0 >= 0)   & (x0 < WW);
    bool xv1 = (x0+1 >= 0) & (x0+1 < WW);
    if (yv0 & xv0) { size_t o = (size_t)(4*y0+1)*FWW + (4*x0+1);
        v00 = 0.25f*(mn[o]+mn[o+1]+mn[o+FWW]+mn[o+FWW+1]); }
    if (yv0 & xv1) { size_t o = (size_t)(4*y0+1)*FWW + (4*(x0+1)+1);
        v01 = 0.25f*(mn[o]+mn[o+1]+mn[o+FWW]+mn[o+FWW+1]); }
    if (yv1 & xv0) { size_t o = (size_t)(4*(y0+1)+1)*FWW + (4*x0+1);
        v10 = 0.25f*(mn[o]+mn[o+1]+mn[o+FWW]+mn[o+FWW+1]); }
    if (yv1 & xv1) { size_t o = (size_t)(4*(y0+1)+1)*FWW + (4*(x0+1)+1);
        v11 = 0.25f*(mn[o]+mn[o+1]+mn[o+FWW]+mn[o+FWW+1]); }

    float rm1n = v00*(1.f-wx)*(1.f-wy) + v01*wx*(1.f-wy)
               + v10*(1.f-wx)*wy       + v11*wx*wy;

    float s = rm1 + rm1n;
    if (s == 0.0f) s = 1e-6f;
    float a = rm1 / s;
    float b = rm1n / s;

    int x0c = min(max(x0, 0), WW-1);
    int x1c = min(max(x0+1, 0), WW-1);
    int y0c = min(max(y0, 0), HH-1);
    int y1c = min(max(y0+1, 0), HH-1);

    float w00 = (yv0 & xv0) ? b*(1.f-wx)*(1.f-wy) : 0.f;
    float w01 = (yv0 & xv1) ? b*wx*(1.f-wy)       : 0.f;
    float w10 = (yv1 & xv0) ? b*(1.f-wx)*wy       : 0.f;
    float w11 = (yv1 & xv1) ? b*wx*wy             : 0.f;

    g_w[idx] = make_float4(w00, w01, w10, w11);
    g_o[idx] = make_int4(y0c*WW + x0c, x1c - x0c, (y1c - y0c)*WW,
                         __float_as_int(a));
}

// -------------------------------------------------------------------------
// Kernel 2: fused = a*fmap1 + sum(w_i * fmap1n taps).
// 8x32-pixel tiles. The block stages ALL CH=16 channel 16x40 fmap1n windows
// into 40KB smem up front (40 independent coalesced loads/thread), takes ONE
// barrier, then runs 16 barrier-free channel iterations with LDS taps.
// Out-of-window outliers (≈never for this data) use the identical global path.
// -------------------------------------------------------------------------
__global__ void __launch_bounds__(256) fuse_kernel(
        const float* __restrict__ fmap1,
        const float* __restrict__ fmap1n,
        float* __restrict__ out)
{
    __shared__ float sbuf[CH][WIN_N];   // 16 * 640 * 4B = 40 KB

    int tid  = threadIdx.x;
    int tile = blockIdx.x;                 // 0..TILES-1
    int tx   = tile % (WW / TS_X);
    int ty   = tile / (WW / TS_X);
    int n     = blockIdx.y / CHUNKS;
    int cbase = (blockIdx.y % CHUNKS) * CH;

    int row = ty * TS_Y + (tid >> 5);
    int col = tx * TS_X + (tid & 31);
    int p   = row * WW + col;

    int RL = ty * TS_Y - MARG;
    int CL = tx * TS_X - MARG;

    size_t plane = ((size_t)(n * CC + cbase)) * HWc;
    const float* fn = fmap1n + plane;

    // ---- stage all 16 windows (no barriers inside; max MLP) ----
    #pragma unroll 8
    for (int k = 0; k < STAGE_ITERS; k++) {
        int e   = tid + k * 256;
        int ch  = e / WIN_N;
        int pos = e - ch * WIN_N;
        int rr  = pos / WIN_X;
        int cc  = pos - rr * WIN_X;
        int gr  = min(max(RL + rr, 0), HH - 1);
        int gc  = min(max(CL + cc, 0), WW - 1);
        sbuf[ch][pos] = fn[(size_t)ch * HWc + gr * WW + gc];
    }

    // per-pixel params (overlaps with staging loads)
    float4 wv = g_w[n * HWc + p];
    int4   ov = g_o[n * HWc + p];
    float  a  = __int_as_float(ov.w);
    int o00 = ov.x, dx = ov.y, dyw = ov.z;

    int iy  = o00 / WW;
    int ix  = o00 - iy * WW;
    int dy1 = (dyw != 0) ? 1 : 0;
    bool inw = (iy >= RL) & (iy + dy1 <= RL + WIN_Y - 1)
             & (ix >= CL) & (ix + dx  <= CL + WIN_X - 1);
    int s00 = (iy - RL) * WIN_X + (ix - CL);
    int sdy = dy1 * WIN_X;

    __syncthreads();   // the ONLY barrier

    const float* f1 = fmap1 + plane + p;
    float*       o  = out   + plane + p;

    if (inw) {
        #pragma unroll 8
        for (int c = 0; c < CH; c++) {
            float t00 = sbuf[c][s00];
            float t01 = sbuf[c][s00 + dx];
            float t10 = sbuf[c][s00 + sdy];
            float t11 = sbuf[c][s00 + sdy + dx];
            float r = a * f1[0]
                    + wv.x * t00 + wv.y * t01 + wv.z * t10 + wv.w * t11;
            o[0] = r;
            f1 += HWc; o += HWc;
        }
    } else {
        const float* fnp = fn;
        #pragma unroll 4
        for (int c = 0; c < CH; c++) {
            float t00 = fnp[o00];
            float t01 = fnp[o00 + dx];
            float t10 = fnp[o00 + dyw];
            float t11 = fnp[o00 + dyw + dx];
            float r = a * f1[0]
                    + wv.x * t00 + wv.y * t01 + wv.z * t10 + wv.w * t11;
            o[0] = r;
            f1 += HWc; fnp += HWc; o += HWc;
        }
    }
}

// -------------------------------------------------------------------------
// Kernel 3: convex upsample of coarse flow channel 0, factor 4.
// One thread per (n, yf, w): produces the 4 fx outputs (contiguous float4).
// -------------------------------------------------------------------------
__global__ void upsample_kernel(const float* __restrict__ cflow,
                                const float* __restrict__ umask,
                                float* __restrict__ out)
{
    int idx = blockIdx.x * blockDim.x + threadIdx.x;
    int total = NB * FHH * WW;
    if (idx >= total) return;
    int w  = idx % WW;
    int yf = (idx / WW) % FHH;
    int n  = idx / (WW * FHH);
    int h = yf >> 2, fy = yf & 3;

    const float* fb = cflow + (size_t)n * 2 * HWc;
    float fv[9];
    #pragma unroll
    for (int k = 0; k < 9; k++) {
        int dy = k / 3 - 1, dxk = k % 3 - 1;
        int hh = h + dy, ww = w + dxk;
        fv[k] = ((hh >= 0) & (hh < HH) & (ww >= 0) & (ww < WW))
                  ? fb[hh * WW + ww] : 0.f;
    }

    const float* mb = umask + (size_t)n * 144 * HWc
                            + (size_t)(fy * 4) * HWc
                            + (size_t)h * WW + w;
    float4 res;
    float* resp = (float*)&res;
    #pragma unroll
    for (int fx = 0; fx < 4; fx++) {
        float m[9];
        float mx = -1e30f;
        #pragma unroll
        for (int k = 0; k < 9; k++) {
            m[k] = mb[(size_t)(k * 16 + fx) * HWc];
            mx = fmaxf(mx, m[k]);
        }
        float num = 0.f, den = 0.f;
        #pragma unroll
        for (int k = 0; k < 9; k++) {
            float e = __expf(m[k] - mx);
            den += e;
            num += e * fv[k];
        }
        resp[fx] = 4.0f * num / den;
    }

    float4* op = (float4*)(out + (size_t)n * FHW + (size_t)yf * FWW + 4 * w);
    *op = res;
}

// -------------------------------------------------------------------------
extern "C" void kernel_launch(void* const* d_in, const int* in_sizes, int n_in,
                              void* d_out, int out_size)
{
    const float* fmap1   = (const float*)d_in[0];
    const float* fmap1n  = (const float*)d_in[1];
    const float* flow    = (const float*)d_in[2];
    const float* mask1   = (const float*)d_in[3];
    const float* mask1n  = (const float*)d_in[4];
    const float* cflow   = (const float*)d_in[5];
    const float* umask   = (const float*)d_in[6];

    float* out_fused = (float*)d_out;
    float* out_flow  = out_fused + FUSED_ELEMS;

    const int T = 256;
    params_kernel<<<(NHW + T - 1) / T, T>>>(flow, mask1, mask1n);

    dim3 fg(TILES, NB * CHUNKS);   // (240, 128)
    fuse_kernel<<<fg, 256>>>(fmap1, fmap1n, out_fused);

    int utotal = NB * FHH * WW;
    upsample_kernel<<<(utotal + T - 1) / T, T>>>(cflow, umask, out_flow);
}

// round 9
// speedup vs baseline: 1.6373x; 1.6373x over previous
#include <cuda_runtime.h>
#include <math.h>

#define NB   8
#define CC   256
#define HH   192
#define WW   320
#define FHH  768
#define FWW  1280
#define HWc  (HH*WW)          // 61440 coarse pixels
#define NHW  (NB*HWc)         // 491520
#define FHW  (FHH*FWW)        // 983040 fine pixels
#define FUSED_ELEMS ((size_t)NB*CC*HWc)   // 125,829,120
#define CH   16               // channels per fuse block
#define CHUNKS (CC/CH)        // 16
#define FUSE_BLOCKS  (HWc/256 * NB * CHUNKS)   // 240*128 = 30720
#define UP_BLOCKS    (NB*FHH*WW/256)           // 7680
#define ALL_BLOCKS   (FUSE_BLOCKS + UP_BLOCKS) // 38400 = 5 * 7680

// Precomputed per-(n,h,w):
//   g_w: (b*w00, b*w01, b*w10, b*w11) — bilinear weights * rm1n/s, invalid taps zeroed
//   g_o: (off00, dx, dyW, float_as_int(a)) — clamped tap base + steps + rm1/s
__device__ float4 g_w[NHW];
__device__ int4   g_o[NHW];

// -------------------------------------------------------------------------
// Kernel 1: per coarse pixel param computation.
// Bilinear resize 768x1280 -> 192x320 is exactly the mean of the 2x2 block
// at (4h+1, 4w+1) (fractional weights are exactly 0.5).
// -------------------------------------------------------------------------
__global__ void params_kernel(const float* __restrict__ flow,
                              const float* __restrict__ mask1,
                              const float* __restrict__ mask1n)
{
    int idx = blockIdx.x * blockDim.x + threadIdx.x;
    if (idx >= NHW) return;
    int w = idx % WW;
    int h = (idx / WW) % HH;
    int n = idx / HWc;

    size_t o00 = (size_t)(4*h + 1) * FWW + (4*w + 1);

    const float* flx = flow + (size_t)n * 2 * FHW;
    const float* fly = flx + (size_t)FHW;
    float rfx = 0.0625f * (flx[o00] + flx[o00+1] + flx[o00+FWW] + flx[o00+FWW+1]);
    float rfy = 0.0625f * (fly[o00] + fly[o00+1] + fly[o00+FWW] + fly[o00+FWW+1]);

    float px = ((float)w + rfx) * ((float)WW / (float)(WW-1)) - 0.5f;
    float py = ((float)h + rfy) * ((float)HH / (float)(HH-1)) - 0.5f;

    const float* m1 = mask1 + (size_t)n * FHW;
    float rm1 = 0.25f * (m1[o00] + m1[o00+1] + m1[o00+FWW] + m1[o00+FWW+1]);

    int   x0 = (int)floorf(px);
    int   y0 = (int)floorf(py);
    float wx = px - (float)x0;
    float wy = py - (float)y0;

    const float* mn = mask1n + (size_t)n * FHW;
    float v00 = 0.f, v01 = 0.f, v10 = 0.f, v11 = 0.f;
    bool yv0 = (y0 >= 0)   & (y0 < HH);
    bool yv1 = (y0+1 >= 0) & (y0+1 < HH);
    bool xv0 = (x0 >= 0)   & (x0 < WW);
    bool xv1 = (x0+1 >= 0) & (x0+1 < WW);
    if (yv0 & xv0) { size_t o = (size_t)(4*y0+1)*FWW + (4*x0+1);
        v00 = 0.25f*(mn[o]+mn[o+1]+mn[o+FWW]+mn[o+FWW+1]); }
    if (yv0 & xv1) { size_t o = (size_t)(4*y0+1)*FWW + (4*(x0+1)+1);
        v01 = 0.25f*(mn[o]+mn[o+1]+mn[o+FWW]+mn[o+FWW+1]); }
    if (yv1 & xv0) { size_t o = (size_t)(4*(y0+1)+1)*FWW + (4*x0+1);
        v10 = 0.25f*(mn[o]+mn[o+1]+mn[o+FWW]+mn[o+FWW+1]); }
    if (yv1 & xv1) { size_t o = (size_t)(4*(y0+1)+1)*FWW + (4*(x0+1)+1);
        v11 = 0.25f*(mn[o]+mn[o+1]+mn[o+FWW]+mn[o+FWW+1]); }

    float rm1n = v00*(1.f-wx)*(1.f-wy) + v01*wx*(1.f-wy)
               + v10*(1.f-wx)*wy       + v11*wx*wy;

    float s = rm1 + rm1n;
    if (s == 0.0f) s = 1e-6f;
    float a = rm1 / s;
    float b = rm1n / s;

    int x0c = min(max(x0, 0), WW-1);
    int x1c = min(max(x0+1, 0), WW-1);
    int y0c = min(max(y0, 0), HH-1);
    int y1c = min(max(y0+1, 0), HH-1);

    float w00 = (yv0 & xv0) ? b*(1.f-wx)*(1.f-wy) : 0.f;
    float w01 = (yv0 & xv1) ? b*wx*(1.f-wy)       : 0.f;
    float w10 = (yv1 & xv0) ? b*(1.f-wx)*wy       : 0.f;
    float w11 = (yv1 & xv1) ? b*wx*wy             : 0.f;

    g_w[idx] = make_float4(w00, w01, w10, w11);
    g_o[idx] = make_int4(y0c*WW + x0c, x1c - x0c, (y1c - y0c)*WW,
                         __float_as_int(a));
}

// -------------------------------------------------------------------------
// Fuse block body: identical math/structure to the best (R6) fuse kernel.
// -------------------------------------------------------------------------
__device__ __forceinline__ void fuse_block(
        int fidx,
        const float* __restrict__ fmap1,
        const float* __restrict__ fmap1n,
        float* __restrict__ out)
{
    int bx    = fidx % (HWc / 256);       // 0..239 spatial block
    int by    = fidx / (HWc / 256);       // 0..127 (n * CHUNKS + chunk)
    int sp    = bx * 256 + threadIdx.x;
    int n     = by / CHUNKS;
    int cbase = (by % CHUNKS) * CH;

    float4 wv = g_w[n * HWc + sp];
    int4   ov = g_o[n * HWc + sp];
    float  a  = __int_as_float(ov.w);
    int o00 = ov.x, dx = ov.y, dyw = ov.z;

    size_t plane = ((size_t)(n * CC + cbase)) * HWc;
    const float* f1 = fmap1  + plane + sp;
    const float* fn = fmap1n + plane;
    float*       o  = out    + plane + sp;

    #pragma unroll 4
    for (int c = 0; c < CH; c++) {
        float t00 = fn[o00];
        float t01 = fn[o00 + dx];
        float t10 = fn[o00 + dyw];
        float t11 = fn[o00 + dyw + dx];
        float r = a * f1[0]
                + wv.x * t00 + wv.y * t01 + wv.z * t10 + wv.w * t11;
        o[0] = r;
        f1 += HWc; fn += HWc; o += HWc;
    }
}

// -------------------------------------------------------------------------
// Upsample block body: convex upsample of coarse flow channel 0, factor 4.
// One thread per (n, yf, w): produces the 4 fx outputs (contiguous float4).
// -------------------------------------------------------------------------
__device__ __forceinline__ void upsample_block(
        int uidx,
        const float* __restrict__ cflow,
        const float* __restrict__ umask,
        float* __restrict__ out)
{
    int idx = uidx * 256 + threadIdx.x;
    int w  = idx % WW;
    int yf = (idx / WW) % FHH;
    int n  = idx / (WW * FHH);
    int h = yf >> 2, fy = yf & 3;

    const float* fb = cflow + (size_t)n * 2 * HWc;
    float fv[9];
    #pragma unroll
    for (int k = 0; k < 9; k++) {
        int dy = k / 3 - 1, dxk = k % 3 - 1;
        int hh = h + dy, ww = w + dxk;
        fv[k] = ((hh >= 0) & (hh < HH) & (ww >= 0) & (ww < WW))
                  ? fb[hh * WW + ww] : 0.f;
    }

    const float* mb = umask + (size_t)n * 144 * HWc
                            + (size_t)(fy * 4) * HWc
                            + (size_t)h * WW + w;
    float4 res;
    float* resp = (float*)&res;
    #pragma unroll
    for (int fx = 0; fx < 4; fx++) {
        float m[9];
        float mx = -1e30f;
        #pragma unroll
        for (int k = 0; k < 9; k++) {
            m[k] = mb[(size_t)(k * 16 + fx) * HWc];
            mx = fmaxf(mx, m[k]);
        }
        float num = 0.f, den = 0.f;
        #pragma unroll
        for (int k = 0; k < 9; k++) {
            float e = __expf(m[k] - mx);
            den += e;
            num += e * fv[k];
        }
        resp[fx] = 4.0f * num / den;
    }

    float4* op = (float4*)(out + FUSED_ELEMS
                               + (size_t)n * FHW + (size_t)yf * FWW + 4 * w);
    *op = res;
}

// -------------------------------------------------------------------------
// Kernel 2: merged fuse + upsample. Every 5th block (b%5==4) runs an
// upsample block; the rest run fuse blocks (exact 4:1 ratio). The DRAM-
// streaming upsample work overlaps the L1tex-heavy fuse gather, using
// bandwidth fuse leaves idle instead of serializing after it.
// -------------------------------------------------------------------------
__global__ void __launch_bounds__(256) merged_kernel(
        const float* __restrict__ fmap1,
        const float* __restrict__ fmap1n,
        const float* __restrict__ cflow,
        const float* __restrict__ umask,
        float* __restrict__ out)
{
    int b = blockIdx.x;
    int q = b / 5;
    int r = b - q * 5;
    if (r == 4) {
        upsample_block(q, cflow, umask, out);
    } else {
        fuse_block(q * 4 + r, fmap1, fmap1n, out);
    }
}

// -------------------------------------------------------------------------
extern "C" void kernel_launch(void* const* d_in, const int* in_sizes, int n_in,
                              void* d_out, int out_size)
{
    const float* fmap1   = (const float*)d_in[0];
    const float* fmap1n  = (const float*)d_in[1];
    const float* flow    = (const float*)d_in[2];
    const float* mask1   = (const float*)d_in[3];
    const float* mask1n  = (const float*)d_in[4];
    const float* cflow   = (const float*)d_in[5];
    const float* umask   = (const float*)d_in[6];

    float* out = (float*)d_out;

    const int T = 256;
    params_kernel<<<(NHW + T - 1) / T, T>>>(flow, mask1, mask1n);
    merged_kernel<<<ALL_BLOCKS, T>>>(fmap1, fmap1n, cflow, umask, out);
}